// round 8
// baseline (speedup 1.0000x reference)
#include <cuda_runtime.h>
#include <cuda_bf16.h>

// Problem constants (SIZE = (128,128,256), B = 4096). Inputs are float32
// (explicit dtype in the reference). Output written as float32 coords.
#define F_DIM 256
#define M_TOTAL 16384
#define B_MAX 4096

#define BM 128
#define BN 128
#define BK 8
#define NCBLK (M_TOTAL / BN)   // 128

__device__ unsigned long long g_best[B_MAX];   // packed (key<<32 | idx)

// Monotone float -> uint map (no NaNs in this workload)
__device__ __forceinline__ unsigned int float_key(float s) {
    unsigned int b = __float_as_uint(s);
    return b ^ ((b & 0x80000000u) ? 0xFFFFFFFFu : 0x80000000u);
}

// ---------------------------------------------------------------------------
__global__ void som_init_kernel(int B) {
    int i = blockIdx.x * blockDim.x + threadIdx.x;
    if (i < B) g_best[i] = 0xFFFFFFFFFFFFFFFFull;
}

// ---------------------------------------------------------------------------
// Fused SGEMM + per-row block argmin + packed atomicMin.
// score = sum(w^2) - 2*x.w   (per-row x^2 constant cannot change the argmin;
// w^2 accumulated inline, so no cross-kernel data dependency besides g_best).
// 256 threads, 8x8 register tile per thread, single-buffered scalar smem.
// ---------------------------------------------------------------------------
__global__ void som_gemm_kernel(const float* __restrict__ x,
                                const float* __restrict__ w) {
    __shared__ float As[BK][BM];     // As[k][row] = x[row][k]
    __shared__ float Bs[BK][BN];     // Bs[k][col] = w[col][k]
    __shared__ float sval[BM][17];   // padded column-reduce staging
    __shared__ int   sidx[BM][17];

    const int tid = threadIdx.x;     // 0..255
    const int bx  = blockIdx.x;      // codebook block (0..127)
    const int by  = blockIdx.y;      // batch block    (0..31)

    const int lrow = tid >> 1;           // 0..127
    const int lc4  = (tid & 1) * 4;      // 0 or 4
    const float* xg = x + (size_t)(by * BM + lrow) * F_DIM + lc4;
    const float* wg = w + (size_t)(bx * BN + lrow) * F_DIM + lc4;

    const int ty = tid >> 4;             // 0..15 -> 8 batch rows
    const int tx = tid & 15;             // 0..15 -> 8 codebook cols

    float acc[8][8];
    float wsq[8];
    for (int i = 0; i < 8; i++) {
        wsq[i] = 0.f;
        for (int j = 0; j < 8; j++) acc[i][j] = 0.f;
    }

    const int NKT = F_DIM / BK;          // 32 k-slabs
    for (int kt = 0; kt < NKT; kt++) {
        __syncthreads();
        {
            const float* xp = xg + kt * BK;
            const float* wp = wg + kt * BK;
            for (int q = 0; q < 4; q++) {
                As[lc4 + q][lrow] = xp[q];
                Bs[lc4 + q][lrow] = wp[q];
            }
        }
        __syncthreads();

        for (int k = 0; k < BK; k++) {
            float a[8], b[8];
            for (int i = 0; i < 8; i++) a[i] = As[k][ty * 8 + i];
            for (int j = 0; j < 8; j++) b[j] = Bs[k][tx * 8 + j];
            for (int j = 0; j < 8; j++) wsq[j] += b[j] * b[j];
            for (int i = 0; i < 8; i++)
                for (int j = 0; j < 8; j++)
                    acc[i][j] += a[i] * b[j];
        }
    }

    // Per-thread epilogue: min over the 8 owned cols per row (strict <:
    // first-occurrence, matching jnp.argmin semantics).
    const int col0 = bx * BN + tx * 8;
    for (int i = 0; i < 8; i++) {
        float mv = wsq[0] - 2.f * acc[i][0];
        int   mj = 0;
        for (int j = 1; j < 8; j++) {
            float s = wsq[j] - 2.f * acc[i][j];
            if (s < mv) { mv = s; mj = j; }
        }
        sval[ty * 8 + i][tx] = mv;
        sidx[ty * 8 + i][tx] = col0 + mj;
    }
    __syncthreads();

    // One thread per row combines the 16 partials; one packed atomicMin.
    // Ties in score resolve to the smaller index via the low 32 bits.
    if (tid < BM) {
        float mv = sval[tid][0];
        int   mi = sidx[tid][0];
        for (int t = 1; t < 16; t++) {
            float v  = sval[tid][t];
            int   ii = sidx[tid][t];
            if (v < mv || (v == mv && ii < mi)) { mv = v; mi = ii; }
        }
        const int grow = by * BM + tid;
        unsigned long long key =
            ((unsigned long long)float_key(mv) << 32) | (unsigned int)mi;
        atomicMin(&g_best[grow], key);
    }
}

// ---------------------------------------------------------------------------
// Finish: unpack g_best -> BMU grid coords, written as FLOAT32.
// (Hypothesis from 4x rel_err == exactly 1.0: the output buffer is compared
// as float32; int writes read as denormals ~ 0 gave ||ref||/||ref|| = 1.0.)
// Coordinates are <= 127, exactly representable in fp32.
// ---------------------------------------------------------------------------
__global__ void som_finish_kernel(float* __restrict__ out, int B) {
    int i = blockIdx.x * blockDim.x + threadIdx.x;
    if (i >= B) return;
    int idx = (int)(g_best[i] & 0xFFFFFFFFull);
    out[i * 2 + 0] = (float)(idx >> 7);    // min_idx / 128
    out[i * 2 + 1] = (float)(idx & 127);   // min_idx % 128
}

// ---------------------------------------------------------------------------
extern "C" void kernel_launch(void* const* d_in, const int* in_sizes, int n_in,
                              void* d_out, int out_size) {
    // Size-based input dispatch (xb: 1,048,576 elems; weights: 4,194,304).
    const float* xb;
    const float* w;
    int nx;
    if (in_sizes[0] <= in_sizes[1]) {
        xb = (const float*)d_in[0]; nx = in_sizes[0];
        w  = (const float*)d_in[1];
    } else {
        xb = (const float*)d_in[1]; nx = in_sizes[1];
        w  = (const float*)d_in[0];
    }
    float* out = (float*)d_out;

    const int B = nx / F_DIM;            // 4096

    som_init_kernel<<<(B + 255) / 256, 256>>>(B);

    dim3 grid(NCBLK, B / BM);            // (128, 32)
    som_gemm_kernel<<<grid, 256>>>(xb, w);

    som_finish_kernel<<<(B + 255) / 256, 256>>>(out, B);
}

// round 10
// speedup vs baseline: 1.5639x; 1.5639x over previous
#include <cuda_runtime.h>
#include <cuda_bf16.h>

// SOM forward (SIZE = (128,128,256), B = 4096), fp32 in, fp32 coords out.
#define F_DIM 256
#define M_TOTAL 16384
#define B_MAX 4096

#define BM 128
#define BN 128
#define BK 8
#define NCBLK (M_TOTAL / BN)   // 128

__device__ float g_wsq[M_TOTAL];               // codebook squared norms
__device__ unsigned long long g_best[B_MAX];   // packed (key<<32 | idx)

// Monotone float -> uint map (no NaNs in this workload)
__device__ __forceinline__ unsigned int float_key(float s) {
    unsigned int b = __float_as_uint(s);
    return b ^ ((b & 0x80000000u) ? 0xFFFFFFFFu : 0x80000000u);
}

// ---------------------------------------------------------------------------
// Init: reset per-row best slots (required every call: graph replays).
// ---------------------------------------------------------------------------
__global__ void som_init_kernel(int B) {
    int i = blockIdx.x * blockDim.x + threadIdx.x;
    if (i < B) g_best[i] = 0xFFFFFFFFFFFFFFFFull;
}

// ---------------------------------------------------------------------------
// wsq[m] = sum_f w[m][f]^2. One warp per codebook row, float4 loads.
// ---------------------------------------------------------------------------
__global__ void som_wsq_kernel(const float* __restrict__ w) {
    int row  = (blockIdx.x * blockDim.x + threadIdx.x) >> 5;
    int lane = threadIdx.x & 31;
    if (row >= M_TOTAL) return;
    const float4* p = reinterpret_cast<const float4*>(w + (size_t)row * F_DIM);
    float s = 0.f;
    #pragma unroll
    for (int c = lane; c < F_DIM / 4; c += 32) {
        float4 v = p[c];
        s += v.x * v.x + v.y * v.y + v.z * v.z + v.w * v.w;
    }
    #pragma unroll
    for (int off = 16; off; off >>= 1) s += __shfl_down_sync(0xffffffffu, s, off);
    if (lane == 0) g_wsq[row] = s;
}

// ---------------------------------------------------------------------------
// Fused SGEMM + per-row block argmin + packed atomicMin.
// score = wsq - 2*x.w (per-row x^2 constant cannot change the argmin).
// 256 threads, 8x8 register tile, double-buffered smem, float4 everywhere.
// ---------------------------------------------------------------------------
__global__ __launch_bounds__(256, 2)
void som_gemm_kernel(const float* __restrict__ x, const float* __restrict__ w) {
    __shared__ __align__(16) float As[2][BK][BM];   // As[b][k][row] = x[row][k]
    __shared__ __align__(16) float Bs[2][BK][BN];   // Bs[b][k][col] = w[col][k]
    __shared__ float sval[BM][17];                  // padded reduce staging
    __shared__ int   sidx[BM][17];

    const int tid = threadIdx.x;     // 0..255
    const int bx  = blockIdx.x;      // codebook block (0..127)
    const int by  = blockIdx.y;      // batch block    (0..31)

    // global->smem mapping: each thread owns one float4 of A and one of B
    const int lrow = tid >> 1;            // 0..127
    const int lc4  = (tid & 1) * 4;       // 0 or 4
    const float* xg = x + (size_t)(by * BM + lrow) * F_DIM + lc4;
    const float* wg = w + (size_t)(bx * BN + lrow) * F_DIM + lc4;

    const int ty = tid >> 4;              // 0..15 -> 8 batch rows
    const int tx = tid & 15;              // 0..15 -> 8 codebook cols

    float acc[8][8];
    #pragma unroll
    for (int i = 0; i < 8; i++)
        #pragma unroll
        for (int j = 0; j < 8; j++) acc[i][j] = 0.f;

    // preload k-slab 0
    {
        float4 av = *reinterpret_cast<const float4*>(xg);
        float4 bv = *reinterpret_cast<const float4*>(wg);
        As[0][lc4 + 0][lrow] = av.x; As[0][lc4 + 1][lrow] = av.y;
        As[0][lc4 + 2][lrow] = av.z; As[0][lc4 + 3][lrow] = av.w;
        Bs[0][lc4 + 0][lrow] = bv.x; Bs[0][lc4 + 1][lrow] = bv.y;
        Bs[0][lc4 + 2][lrow] = bv.z; Bs[0][lc4 + 3][lrow] = bv.w;
    }
    __syncthreads();

    const int NKT = F_DIM / BK;           // 32
    for (int kt = 0; kt < NKT; kt++) {
        const int cur = kt & 1;
        float4 an, bn;
        if (kt < NKT - 1) {               // register-staged prefetch
            an = *reinterpret_cast<const float4*>(xg + (kt + 1) * BK);
            bn = *reinterpret_cast<const float4*>(wg + (kt + 1) * BK);
        }
        #pragma unroll
        for (int k = 0; k < BK; k++) {
            float a[8], b[8];
            *reinterpret_cast<float4*>(&a[0]) =
                *reinterpret_cast<const float4*>(&As[cur][k][ty * 8]);
            *reinterpret_cast<float4*>(&a[4]) =
                *reinterpret_cast<const float4*>(&As[cur][k][ty * 8 + 4]);
            *reinterpret_cast<float4*>(&b[0]) =
                *reinterpret_cast<const float4*>(&Bs[cur][k][tx * 8]);
            *reinterpret_cast<float4*>(&b[4]) =
                *reinterpret_cast<const float4*>(&Bs[cur][k][tx * 8 + 4]);
            #pragma unroll
            for (int i = 0; i < 8; i++)
                #pragma unroll
                for (int j = 0; j < 8; j++)
                    acc[i][j] += a[i] * b[j];
        }
        if (kt < NKT - 1) {
            const int nxt = cur ^ 1;
            As[nxt][lc4 + 0][lrow] = an.x; As[nxt][lc4 + 1][lrow] = an.y;
            As[nxt][lc4 + 2][lrow] = an.z; As[nxt][lc4 + 3][lrow] = an.w;
            Bs[nxt][lc4 + 0][lrow] = bn.x; Bs[nxt][lc4 + 1][lrow] = bn.y;
            Bs[nxt][lc4 + 2][lrow] = bn.z; Bs[nxt][lc4 + 3][lrow] = bn.w;
            __syncthreads();
        }
    }

    // Epilogue: score = wsq - 2*dot; per-thread min over owned 8 cols per row
    // (strict <: first-occurrence, matching jnp.argmin).
    const int col0 = bx * BN + tx * 8;
    float wq[8];
    #pragma unroll
    for (int j = 0; j < 8; j++) wq[j] = g_wsq[col0 + j];

    #pragma unroll
    for (int i = 0; i < 8; i++) {
        float mv = wq[0] - 2.f * acc[i][0];
        int   mj = 0;
        #pragma unroll
        for (int j = 1; j < 8; j++) {
            float s = wq[j] - 2.f * acc[i][j];
            if (s < mv) { mv = s; mj = j; }
        }
        sval[ty * 8 + i][tx] = mv;
        sidx[ty * 8 + i][tx] = col0 + mj;
    }
    __syncthreads();

    // One thread per row combines 16 partials; ties -> smaller index (packed
    // key low bits preserve that under atomicMin as well).
    if (tid < BM) {
        float mv = sval[tid][0];
        int   mi = sidx[tid][0];
        #pragma unroll
        for (int t = 1; t < 16; t++) {
            float v  = sval[tid][t];
            int   ii = sidx[tid][t];
            if (v < mv || (v == mv && ii < mi)) { mv = v; mi = ii; }
        }
        const int grow = by * BM + tid;
        unsigned long long key =
            ((unsigned long long)float_key(mv) << 32) | (unsigned int)mi;
        atomicMin(&g_best[grow], key);
    }
}

// ---------------------------------------------------------------------------
// Finish: unpack g_best -> BMU grid coords, written as FLOAT32 (harness
// compares d_out as float32 — proven in R8).
// ---------------------------------------------------------------------------
__global__ void som_finish_kernel(float* __restrict__ out, int B) {
    int i = blockIdx.x * blockDim.x + threadIdx.x;
    if (i >= B) return;
    int idx = (int)(g_best[i] & 0xFFFFFFFFull);
    out[i * 2 + 0] = (float)(idx >> 7);    // min_idx / 128
    out[i * 2 + 1] = (float)(idx & 127);   // min_idx % 128
}

// ---------------------------------------------------------------------------
extern "C" void kernel_launch(void* const* d_in, const int* in_sizes, int n_in,
                              void* d_out, int out_size) {
    // Size-based input dispatch (xb: 1,048,576 elems; weights: 4,194,304).
    const float* xb;
    const float* w;
    int nx;
    if (in_sizes[0] <= in_sizes[1]) {
        xb = (const float*)d_in[0]; nx = in_sizes[0];
        w  = (const float*)d_in[1];
    } else {
        xb = (const float*)d_in[1]; nx = in_sizes[1];
        w  = (const float*)d_in[0];
    }
    float* out = (float*)d_out;

    const int B = nx / F_DIM;            // 4096

    som_init_kernel<<<(B + 255) / 256, 256>>>(B);
    som_wsq_kernel<<<M_TOTAL / 8, 256>>>(w);

    dim3 grid(NCBLK, B / BM);            // (128, 32)
    som_gemm_kernel<<<grid, 256>>>(xb, w);

    som_finish_kernel<<<(B + 255) / 256, 256>>>(out, B);
}

// round 11
// speedup vs baseline: 2.8340x; 1.8122x over previous
#include <cuda_runtime.h>
#include <cuda_bf16.h>

// SOM forward (SIZE = (128,128,256), B = 4096), fp32 in, fp32 coords out.
// Strategy: TF32 tensor-core GEMM computes approx scores; per (row, 128-col
// tile) keep top-2 candidates; exact fp32 rescore of the few within-margin
// candidates reproduces the exact argmin.
#define F_DIM 256
#define M_TOTAL 16384
#define B_MAX 4096

#define BM 128
#define BN 128
#define KC 16                 // k-chunk staged in smem
#define KCP 18                // padded k-stride (bank-conflict mitigation)
#define NCBLK (M_TOTAL / BN)  // 128 column tiles

#define MARGIN 1.0f           // >> 6x worst-case tf32 dot error (~0.16)

__device__ float g_wsq[M_TOTAL];
// per (row, tile): top-2 packed keys (float_key(score)<<32 | global_col)
__device__ unsigned long long g_top2[B_MAX * NCBLK * 2];

// Monotone float <-> uint order maps (no NaNs in this workload)
__device__ __forceinline__ unsigned int float_key(float s) {
    unsigned int b = __float_as_uint(s);
    return b ^ ((b & 0x80000000u) ? 0xFFFFFFFFu : 0x80000000u);
}
__device__ __forceinline__ float unkey(unsigned int k) {
    return __uint_as_float((k & 0x80000000u) ? (k ^ 0x80000000u) : ~k);
}
__device__ __forceinline__ void top2_ins(unsigned long long& k1,
                                         unsigned long long& k2,
                                         unsigned long long a) {
    if (a < k1) { k2 = k1; k1 = a; }
    else if (a < k2) { k2 = a; }
}

// ---------------------------------------------------------------------------
// wsq[m] = sum_f w[m][f]^2  (exact fp32; used by both filter and rescore)
// ---------------------------------------------------------------------------
__global__ void som_wsq_kernel(const float* __restrict__ w) {
    int row  = (blockIdx.x * blockDim.x + threadIdx.x) >> 5;
    int lane = threadIdx.x & 31;
    if (row >= M_TOTAL) return;
    const float4* p = reinterpret_cast<const float4*>(w + (size_t)row * F_DIM);
    float s = 0.f;
    #pragma unroll
    for (int c = lane; c < F_DIM / 4; c += 32) {
        float4 v = p[c];
        s += v.x * v.x + v.y * v.y + v.z * v.z + v.w * v.w;
    }
    #pragma unroll
    for (int off = 16; off; off >>= 1) s += __shfl_down_sync(0xffffffffu, s, off);
    if (lane == 0) g_wsq[row] = s;
}

// ---------------------------------------------------------------------------
// TF32 tensor GEMM + per-(row,tile) top-2 epilogue.
// CTA: 256 threads = 8 warps; warp_m = wid&1 (64 rows), warp_n = wid>>1
// (32 cols). Each warp: 4x4 m16n8k8 tiles. Double-buffered smem chunks KC=16.
// ---------------------------------------------------------------------------
__global__ __launch_bounds__(256, 2)
void som_tf32_kernel(const float* __restrict__ x, const float* __restrict__ w) {
    __shared__ float As[2][BM][KCP];   // As[b][row][k]
    __shared__ float Bs[2][BN][KCP];   // Bs[b][col][k]
    __shared__ unsigned long long stop2[BM][4][2];  // per row, per warp_n

    const int tid  = threadIdx.x;
    const int bx   = blockIdx.x;       // column tile (0..127)
    const int by   = blockIdx.y;       // row tile    (0..31)
    const int wid  = tid >> 5;
    const int lane = tid & 31;
    const int warp_m = wid & 1;        // 0..1
    const int warp_n = wid >> 1;       // 0..3
    const int m_base = warp_m * 64;
    const int n_base = warp_n * 32;
    const int lg = lane >> 2;          // group id (0..7)
    const int lt = lane & 3;           // thread-in-group (0..3)

    // global->smem chunk loader mapping: idx = tid + s*256 (s=0,1);
    // row = idx>>2, c4 = (idx&3)*4 -> one float4 each
    const int r0 = tid >> 2,        c40 = (tid & 3) * 4;
    const int r1 = (tid + 256) >> 2, c41 = ((tid + 256) & 3) * 4;
    const float* xg0 = x + (size_t)(by * BM + r0) * F_DIM + c40;
    const float* xg1 = x + (size_t)(by * BM + r1) * F_DIM + c41;
    const float* wg0 = w + (size_t)(bx * BN + r0) * F_DIM + c40;
    const float* wg1 = w + (size_t)(bx * BN + r1) * F_DIM + c41;

    float acc[4][4][4];
    #pragma unroll
    for (int mt = 0; mt < 4; mt++)
        #pragma unroll
        for (int nt = 0; nt < 4; nt++)
            #pragma unroll
            for (int r = 0; r < 4; r++) acc[mt][nt][r] = 0.f;

    // preload chunk 0
    {
        float4 a0 = *reinterpret_cast<const float4*>(xg0);
        float4 a1 = *reinterpret_cast<const float4*>(xg1);
        float4 b0 = *reinterpret_cast<const float4*>(wg0);
        float4 b1 = *reinterpret_cast<const float4*>(wg1);
        As[0][r0][c40+0]=a0.x; As[0][r0][c40+1]=a0.y; As[0][r0][c40+2]=a0.z; As[0][r0][c40+3]=a0.w;
        As[0][r1][c41+0]=a1.x; As[0][r1][c41+1]=a1.y; As[0][r1][c41+2]=a1.z; As[0][r1][c41+3]=a1.w;
        Bs[0][r0][c40+0]=b0.x; Bs[0][r0][c40+1]=b0.y; Bs[0][r0][c40+2]=b0.z; Bs[0][r0][c40+3]=b0.w;
        Bs[0][r1][c41+0]=b1.x; Bs[0][r1][c41+1]=b1.y; Bs[0][r1][c41+2]=b1.z; Bs[0][r1][c41+3]=b1.w;
    }
    __syncthreads();

    const int NKC = F_DIM / KC;   // 16 chunks
    for (int kt = 0; kt < NKC; kt++) {
        const int cur = kt & 1;
        float4 pa0, pa1, pb0, pb1;
        if (kt < NKC - 1) {       // register-staged prefetch
            pa0 = *reinterpret_cast<const float4*>(xg0 + (kt + 1) * KC);
            pa1 = *reinterpret_cast<const float4*>(xg1 + (kt + 1) * KC);
            pb0 = *reinterpret_cast<const float4*>(wg0 + (kt + 1) * KC);
            pb1 = *reinterpret_cast<const float4*>(wg1 + (kt + 1) * KC);
        }
        #pragma unroll
        for (int kk = 0; kk < KC; kk += 8) {
            // A fragments (m16n8k8 tf32, row-major A):
            // a0:(lg, lt) a1:(lg+8, lt) a2:(lg, lt+4) a3:(lg+8, lt+4)
            unsigned int afr[4][4];
            #pragma unroll
            for (int mt = 0; mt < 4; mt++) {
                int rr = m_base + mt * 16 + lg;
                afr[mt][0] = __float_as_uint(As[cur][rr    ][kk + lt    ]);
                afr[mt][1] = __float_as_uint(As[cur][rr + 8][kk + lt    ]);
                afr[mt][2] = __float_as_uint(As[cur][rr    ][kk + lt + 4]);
                afr[mt][3] = __float_as_uint(As[cur][rr + 8][kk + lt + 4]);
            }
            // B fragments (col-major k x n): b0:(k=lt, n=lg) b1:(k=lt+4, n=lg)
            unsigned int bfr[4][2];
            #pragma unroll
            for (int nt = 0; nt < 4; nt++) {
                int nn = n_base + nt * 8 + lg;
                bfr[nt][0] = __float_as_uint(Bs[cur][nn][kk + lt    ]);
                bfr[nt][1] = __float_as_uint(Bs[cur][nn][kk + lt + 4]);
            }
            #pragma unroll
            for (int mt = 0; mt < 4; mt++)
                #pragma unroll
                for (int nt = 0; nt < 4; nt++) {
                    asm volatile(
                        "mma.sync.aligned.m16n8k8.row.col.f32.tf32.tf32.f32 "
                        "{%0,%1,%2,%3}, {%4,%5,%6,%7}, {%8,%9}, {%0,%1,%2,%3};\n"
                        : "+f"(acc[mt][nt][0]), "+f"(acc[mt][nt][1]),
                          "+f"(acc[mt][nt][2]), "+f"(acc[mt][nt][3])
                        : "r"(afr[mt][0]), "r"(afr[mt][1]),
                          "r"(afr[mt][2]), "r"(afr[mt][3]),
                          "r"(bfr[nt][0]), "r"(bfr[nt][1]));
                }
        }
        if (kt < NKC - 1) {
            const int nxt = cur ^ 1;
            As[nxt][r0][c40+0]=pa0.x; As[nxt][r0][c40+1]=pa0.y; As[nxt][r0][c40+2]=pa0.z; As[nxt][r0][c40+3]=pa0.w;
            As[nxt][r1][c41+0]=pa1.x; As[nxt][r1][c41+1]=pa1.y; As[nxt][r1][c41+2]=pa1.z; As[nxt][r1][c41+3]=pa1.w;
            Bs[nxt][r0][c40+0]=pb0.x; Bs[nxt][r0][c40+1]=pb0.y; Bs[nxt][r0][c40+2]=pb0.z; Bs[nxt][r0][c40+3]=pb0.w;
            Bs[nxt][r1][c41+0]=pb1.x; Bs[nxt][r1][c41+1]=pb1.y; Bs[nxt][r1][c41+2]=pb1.z; Bs[nxt][r1][c41+3]=pb1.w;
            __syncthreads();
        }
    }

    // Epilogue: approx score = wsq - 2*dot; top-2 per (row, this CTA's tile).
    // D frag: c0,c1 -> (row lg, cols 2*lt+{0,1}); c2,c3 -> (row lg+8, same).
    #pragma unroll
    for (int mt = 0; mt < 4; mt++) {
        #pragma unroll
        for (int h = 0; h < 2; h++) {
            int row_local = m_base + mt * 16 + lg + h * 8;
            unsigned long long k1 = ~0ull, k2 = ~0ull;
            #pragma unroll
            for (int nt = 0; nt < 4; nt++) {
                #pragma unroll
                for (int j = 0; j < 2; j++) {
                    int col_local = n_base + nt * 8 + 2 * lt + j;
                    int col = bx * BN + col_local;
                    float s = g_wsq[col] - 2.f * acc[mt][nt][h * 2 + j];
                    unsigned long long key =
                        ((unsigned long long)float_key(s) << 32) | (unsigned int)col;
                    top2_ins(k1, k2, key);
                }
            }
            // merge across the 4 lanes holding this row (lanes with same lg)
            #pragma unroll
            for (int off = 1; off <= 2; off <<= 1) {
                unsigned long long o1 = __shfl_xor_sync(0xffffffffu, k1, off);
                unsigned long long o2 = __shfl_xor_sync(0xffffffffu, k2, off);
                top2_ins(k1, k2, o1);
                top2_ins(k1, k2, o2);
            }
            if (lt == 0) {
                stop2[row_local][warp_n][0] = k1;
                stop2[row_local][warp_n][1] = k2;
            }
        }
    }
    __syncthreads();

    if (tid < BM) {
        unsigned long long k1 = stop2[tid][0][0], k2 = stop2[tid][0][1];
        #pragma unroll
        for (int wn = 1; wn < 4; wn++) {
            top2_ins(k1, k2, stop2[tid][wn][0]);
            top2_ins(k1, k2, stop2[tid][wn][1]);
        }
        const int grow = by * BM + tid;
        g_top2[((size_t)grow * NCBLK + bx) * 2 + 0] = k1;
        g_top2[((size_t)grow * NCBLK + bx) * 2 + 1] = k2;
    }
}

// ---------------------------------------------------------------------------
// Rescore: per row (one CTA of 128 threads), find approx global min, select
// candidates within MARGIN, exact-fp32-rescore them, emit exact argmin coords.
// ---------------------------------------------------------------------------
__global__ void som_rescore_kernel(const float* __restrict__ x,
                                   const float* __restrict__ w,
                                   float* __restrict__ out) {
    __shared__ float xs[F_DIM];
    __shared__ unsigned long long keys[NCBLK * 2];
    __shared__ unsigned long long gbest;      // approx min (packed)
    __shared__ unsigned long long best;       // exact min (packed)
    __shared__ int cand_cols[NCBLK];
    __shared__ int full_tiles[NCBLK];
    __shared__ int ncand, nfull;

    const int row = blockIdx.x;
    const int tid = threadIdx.x;

    if (tid == 0) { gbest = ~0ull; best = ~0ull; ncand = 0; nfull = 0; }
    // stage x row + candidate keys
    xs[tid]       = x[(size_t)row * F_DIM + tid];
    xs[tid + 128] = x[(size_t)row * F_DIM + tid + 128];
    keys[tid]       = g_top2[((size_t)row * NCBLK) * 2 + tid];
    keys[tid + 128] = g_top2[((size_t)row * NCBLK) * 2 + tid + 128];
    __syncthreads();

    // approx global min (atomicMin on shared; packed order == score order)
    unsigned long long lmin = keys[tid] < keys[tid + 128] ? keys[tid] : keys[tid + 128];
    atomicMin(&gbest, lmin);
    __syncthreads();

    const unsigned int kthresh = float_key(unkey((unsigned int)(gbest >> 32)) + MARGIN);

    // candidate selection: thread t owns tile t
    {
        unsigned long long k1 = keys[2 * tid], k2 = keys[2 * tid + 1];
        if ((unsigned int)(k2 >> 32) < kthresh) {
            full_tiles[atomicAdd(&nfull, 1)] = tid;       // rare fallback
        } else if ((unsigned int)(k1 >> 32) < kthresh) {
            cand_cols[atomicAdd(&ncand, 1)] = (int)(k1 & 0xFFFFFFFFull);
        }
    }
    __syncthreads();

    // exact rescore: full tiles (all 128 cols, one col per thread)
    for (int f = 0; f < nfull; f++) {
        int col = full_tiles[f] * BN + tid;
        const float* wr = w + (size_t)col * F_DIM;
        float dot = 0.f;
        #pragma unroll 8
        for (int k = 0; k < F_DIM; k++) dot += xs[k] * wr[k];
        float s = g_wsq[col] - 2.f * dot;
        unsigned long long key =
            ((unsigned long long)float_key(s) << 32) | (unsigned int)col;
        atomicMin(&best, key);
    }
    // exact rescore: single candidates (one warp per candidate)
    {
        int wid = tid >> 5, lane = tid & 31;
        for (int c = wid; c < ncand; c += 4) {
            int col = cand_cols[c];
            const float* wr = w + (size_t)col * F_DIM;
            float p = 0.f;
            #pragma unroll
            for (int k = lane; k < F_DIM; k += 32) p += xs[k] * wr[k];
            #pragma unroll
            for (int off = 16; off; off >>= 1) p += __shfl_down_sync(0xffffffffu, p, off);
            if (lane == 0) {
                float s = g_wsq[col] - 2.f * p;
                unsigned long long key =
                    ((unsigned long long)float_key(s) << 32) | (unsigned int)col;
                atomicMin(&best, key);
            }
        }
    }
    __syncthreads();

    if (tid == 0) {
        int idx = (int)(best & 0xFFFFFFFFull);
        out[row * 2 + 0] = (float)(idx >> 7);    // min_idx / 128
        out[row * 2 + 1] = (float)(idx & 127);   // min_idx % 128
    }
}

// ---------------------------------------------------------------------------
extern "C" void kernel_launch(void* const* d_in, const int* in_sizes, int n_in,
                              void* d_out, int out_size) {
    // Size-based input dispatch (xb: 1,048,576 elems; weights: 4,194,304).
    const float* xb;
    const float* w;
    int nx;
    if (in_sizes[0] <= in_sizes[1]) {
        xb = (const float*)d_in[0]; nx = in_sizes[0];
        w  = (const float*)d_in[1];
    } else {
        xb = (const float*)d_in[1]; nx = in_sizes[1];
        w  = (const float*)d_in[0];
    }
    float* out = (float*)d_out;
    const int B = nx / F_DIM;            // 4096

    som_wsq_kernel<<<M_TOTAL / 8, 256>>>(w);

    dim3 grid(NCBLK, B / BM);            // (128, 32)
    som_tf32_kernel<<<grid, 256>>>(xb, w);

    som_rescore_kernel<<<B, 128>>>(xb, w, out);
}

// round 12
// speedup vs baseline: 4.3733x; 1.5432x over previous
#include <cuda_runtime.h>
#include <cuda_bf16.h>

// SOM forward (SIZE = (128,128,256), B = 4096), fp32 in, fp32 coords out.
// bf16 tensor-core filter (mma.m16n8k16) + exact fp32 rescore of candidates
// within a provable error margin -> exact argmin.
#define F_DIM 256
#define M_TOTAL 16384
#define B_MAX 4096

#define BM 128
#define BN 128
#define KC 32                 // k-chunk (bf16) staged in smem
#define KCP 36                // padded k-stride in halves
#define NCBLK (M_TOTAL / BN)  // 128 column tiles

#define MARGIN 4.0f           // > worst-case two-sided bf16 dot error (~2.6)

__device__ float g_wsq[M_TOTAL];
__device__ __nv_bfloat16 g_xb[B_MAX * F_DIM];
__device__ __nv_bfloat16 g_wb[M_TOTAL * F_DIM];
// per (row, tile): top-2 packed keys (float_key(score)<<32 | global_col)
__device__ unsigned long long g_top2[B_MAX * NCBLK * 2];

// Monotone float <-> uint order maps (no NaNs in this workload)
__device__ __forceinline__ unsigned int float_key(float s) {
    unsigned int b = __float_as_uint(s);
    return b ^ ((b & 0x80000000u) ? 0xFFFFFFFFu : 0x80000000u);
}
__device__ __forceinline__ float unkey(unsigned int k) {
    return __uint_as_float((k & 0x80000000u) ? (k ^ 0x80000000u) : ~k);
}
__device__ __forceinline__ void top2_ins(unsigned long long& k1,
                                         unsigned long long& k2,
                                         unsigned long long a) {
    if (a < k1) { k2 = k1; k1 = a; }
    else if (a < k2) { k2 = a; }
}

// ---------------------------------------------------------------------------
// Convert x -> bf16. One float4 per thread.
// ---------------------------------------------------------------------------
__global__ void som_convx_kernel(const float* __restrict__ x, int n4) {
    int i = blockIdx.x * blockDim.x + threadIdx.x;
    if (i >= n4) return;
    float4 v = reinterpret_cast<const float4*>(x)[i];
    __nv_bfloat162 p0 = __floats2bfloat162_rn(v.x, v.y);
    __nv_bfloat162 p1 = __floats2bfloat162_rn(v.z, v.w);
    uint2 st = make_uint2(*reinterpret_cast<unsigned int*>(&p0),
                          *reinterpret_cast<unsigned int*>(&p1));
    *reinterpret_cast<uint2*>(&g_xb[i * 4]) = st;
}

// ---------------------------------------------------------------------------
// Convert w -> bf16 AND compute exact fp32 wsq. One warp per codebook row.
// ---------------------------------------------------------------------------
__global__ void som_convw_kernel(const float* __restrict__ w) {
    int row  = (blockIdx.x * blockDim.x + threadIdx.x) >> 5;
    int lane = threadIdx.x & 31;
    if (row >= M_TOTAL) return;
    const float4* p = reinterpret_cast<const float4*>(w + (size_t)row * F_DIM);
    float s = 0.f;
    #pragma unroll
    for (int c = lane; c < F_DIM / 4; c += 32) {
        float4 v = p[c];
        s += v.x * v.x + v.y * v.y + v.z * v.z + v.w * v.w;
        __nv_bfloat162 p0 = __floats2bfloat162_rn(v.x, v.y);
        __nv_bfloat162 p1 = __floats2bfloat162_rn(v.z, v.w);
        uint2 st = make_uint2(*reinterpret_cast<unsigned int*>(&p0),
                              *reinterpret_cast<unsigned int*>(&p1));
        *reinterpret_cast<uint2*>(&g_wb[(size_t)row * F_DIM + c * 4]) = st;
    }
    #pragma unroll
    for (int off = 16; off; off >>= 1) s += __shfl_down_sync(0xffffffffu, s, off);
    if (lane == 0) g_wsq[row] = s;
}

// ---------------------------------------------------------------------------
// bf16 tensor GEMM + per-(row,tile) top-2 epilogue.
// 8 warps: warp_m = wid&1 (64 rows), warp_n = wid>>1 (32 cols); each warp
// 4x4 m16n8k16 tiles. Double-buffered smem, KC=32 halves per chunk.
// ---------------------------------------------------------------------------
__global__ __launch_bounds__(256, 2)
void som_bf16_kernel() {
    __shared__ __align__(16) __nv_bfloat16 As[2][BM][KCP];  // [row][k]
    __shared__ __align__(16) __nv_bfloat16 Bs[2][BN][KCP];  // [col][k]
    __shared__ unsigned long long stop2[BM][4][2];          // per row, warp_n

    const int tid  = threadIdx.x;
    const int bx   = blockIdx.x;       // column tile (0..127)
    const int by   = blockIdx.y;       // row tile    (0..31)
    const int wid  = tid >> 5;
    const int lane = tid & 31;
    const int warp_m = wid & 1;
    const int warp_n = wid >> 1;
    const int m_base = warp_m * 64;
    const int n_base = warp_n * 32;
    const int lg = lane >> 2;          // 0..7
    const int lt = lane & 3;           // 0..3

    // loader mapping: 128 rows x 32 halves = 512 x uint4 per matrix per chunk;
    // thread t loads uint4 (r0,q0) and (r0+64,q0).
    const int r0 = tid >> 2;           // 0..63
    const int q0 = tid & 3;            // 0..3 -> halves q0*8
    const __nv_bfloat16* xg0 = g_xb + (size_t)(by * BM + r0)      * F_DIM + q0 * 8;
    const __nv_bfloat16* xg1 = g_xb + (size_t)(by * BM + r0 + 64) * F_DIM + q0 * 8;
    const __nv_bfloat16* wg0 = g_wb + (size_t)(bx * BN + r0)      * F_DIM + q0 * 8;
    const __nv_bfloat16* wg1 = g_wb + (size_t)(bx * BN + r0 + 64) * F_DIM + q0 * 8;

    float acc[4][4][4];
    #pragma unroll
    for (int mt = 0; mt < 4; mt++)
        #pragma unroll
        for (int nt = 0; nt < 4; nt++)
            #pragma unroll
            for (int r = 0; r < 4; r++) acc[mt][nt][r] = 0.f;

    // store one uint4 (8 halves) as two aligned uint2s (row stride 72B)
    auto st8 = [&](__nv_bfloat16* dst, uint4 v) {
        *reinterpret_cast<uint2*>(dst)     = make_uint2(v.x, v.y);
        *reinterpret_cast<uint2*>(dst + 4) = make_uint2(v.z, v.w);
    };

    // preload chunk 0
    {
        uint4 a0 = *reinterpret_cast<const uint4*>(xg0);
        uint4 a1 = *reinterpret_cast<const uint4*>(xg1);
        uint4 b0 = *reinterpret_cast<const uint4*>(wg0);
        uint4 b1 = *reinterpret_cast<const uint4*>(wg1);
        st8(&As[0][r0     ][q0 * 8], a0);
        st8(&As[0][r0 + 64][q0 * 8], a1);
        st8(&Bs[0][r0     ][q0 * 8], b0);
        st8(&Bs[0][r0 + 64][q0 * 8], b1);
    }
    __syncthreads();

    const int NKC = F_DIM / KC;   // 8 chunks
    for (int kt = 0; kt < NKC; kt++) {
        const int cur = kt & 1;
        uint4 pa0, pa1, pb0, pb1;
        if (kt < NKC - 1) {       // register-staged prefetch
            pa0 = *reinterpret_cast<const uint4*>(xg0 + (kt + 1) * KC);
            pa1 = *reinterpret_cast<const uint4*>(xg1 + (kt + 1) * KC);
            pb0 = *reinterpret_cast<const uint4*>(wg0 + (kt + 1) * KC);
            pb1 = *reinterpret_cast<const uint4*>(wg1 + (kt + 1) * KC);
        }
        #pragma unroll
        for (int ks = 0; ks < KC; ks += 16) {
            // A frags (m16n8k16 bf16): a0=(lg,2lt pair) a1=(lg+8,..)
            // a2=(lg, 2lt+8 pair) a3=(lg+8, ..). Packed bf16 pair = 1 LDS.32.
            unsigned int afr[4][4];
            #pragma unroll
            for (int mt = 0; mt < 4; mt++) {
                int rr = m_base + mt * 16 + lg;
                afr[mt][0] = *reinterpret_cast<const unsigned int*>(&As[cur][rr    ][ks + 2 * lt    ]);
                afr[mt][1] = *reinterpret_cast<const unsigned int*>(&As[cur][rr + 8][ks + 2 * lt    ]);
                afr[mt][2] = *reinterpret_cast<const unsigned int*>(&As[cur][rr    ][ks + 2 * lt + 8]);
                afr[mt][3] = *reinterpret_cast<const unsigned int*>(&As[cur][rr + 8][ks + 2 * lt + 8]);
            }
            // B frags: b0=(k 2lt pair, n lg), b1=(k 2lt+8 pair, n lg)
            unsigned int bfr[4][2];
            #pragma unroll
            for (int nt = 0; nt < 4; nt++) {
                int nn = n_base + nt * 8 + lg;
                bfr[nt][0] = *reinterpret_cast<const unsigned int*>(&Bs[cur][nn][ks + 2 * lt    ]);
                bfr[nt][1] = *reinterpret_cast<const unsigned int*>(&Bs[cur][nn][ks + 2 * lt + 8]);
            }
            #pragma unroll
            for (int mt = 0; mt < 4; mt++)
                #pragma unroll
                for (int nt = 0; nt < 4; nt++) {
                    asm volatile(
                        "mma.sync.aligned.m16n8k16.row.col.f32.bf16.bf16.f32 "
                        "{%0,%1,%2,%3}, {%4,%5,%6,%7}, {%8,%9}, {%0,%1,%2,%3};\n"
                        : "+f"(acc[mt][nt][0]), "+f"(acc[mt][nt][1]),
                          "+f"(acc[mt][nt][2]), "+f"(acc[mt][nt][3])
                        : "r"(afr[mt][0]), "r"(afr[mt][1]),
                          "r"(afr[mt][2]), "r"(afr[mt][3]),
                          "r"(bfr[nt][0]), "r"(bfr[nt][1]));
                }
        }
        if (kt < NKC - 1) {
            const int nxt = cur ^ 1;
            st8(&As[nxt][r0     ][q0 * 8], pa0);
            st8(&As[nxt][r0 + 64][q0 * 8], pa1);
            st8(&Bs[nxt][r0     ][q0 * 8], pb0);
            st8(&Bs[nxt][r0 + 64][q0 * 8], pb1);
            __syncthreads();
        }
    }

    // Epilogue: approx score = wsq - 2*dot; top-2 per (row, tile).
    // D frag: c0,c1 -> (row lg, cols 2lt,2lt+1); c2,c3 -> (row lg+8, same).
    #pragma unroll
    for (int mt = 0; mt < 4; mt++) {
        #pragma unroll
        for (int h = 0; h < 2; h++) {
            int row_local = m_base + mt * 16 + lg + h * 8;
            unsigned long long k1 = ~0ull, k2 = ~0ull;
            #pragma unroll
            for (int nt = 0; nt < 4; nt++) {
                #pragma unroll
                for (int j = 0; j < 2; j++) {
                    int col = bx * BN + n_base + nt * 8 + 2 * lt + j;
                    float s = g_wsq[col] - 2.f * acc[mt][nt][h * 2 + j];
                    unsigned long long key =
                        ((unsigned long long)float_key(s) << 32) | (unsigned int)col;
                    top2_ins(k1, k2, key);
                }
            }
            #pragma unroll
            for (int off = 1; off <= 2; off <<= 1) {
                unsigned long long o1 = __shfl_xor_sync(0xffffffffu, k1, off);
                unsigned long long o2 = __shfl_xor_sync(0xffffffffu, k2, off);
                top2_ins(k1, k2, o1);
                top2_ins(k1, k2, o2);
            }
            if (lt == 0) {
                stop2[row_local][warp_n][0] = k1;
                stop2[row_local][warp_n][1] = k2;
            }
        }
    }
    __syncthreads();

    if (tid < BM) {
        unsigned long long k1 = stop2[tid][0][0], k2 = stop2[tid][0][1];
        #pragma unroll
        for (int wn = 1; wn < 4; wn++) {
            top2_ins(k1, k2, stop2[tid][wn][0]);
            top2_ins(k1, k2, stop2[tid][wn][1]);
        }
        const int grow = by * BM + tid;
        g_top2[((size_t)grow * NCBLK + bx) * 2 + 0] = k1;
        g_top2[((size_t)grow * NCBLK + bx) * 2 + 1] = k2;
    }
}

// ---------------------------------------------------------------------------
// Rescore: per row, approx global min -> candidates within MARGIN -> exact
// fp32 rescore -> exact argmin coords (fp32 output; harness compares fp32).
// ---------------------------------------------------------------------------
__global__ void som_rescore_kernel(const float* __restrict__ x,
                                   const float* __restrict__ w,
                                   float* __restrict__ out) {
    __shared__ float xs[F_DIM];
    __shared__ unsigned long long keys[NCBLK * 2];
    __shared__ unsigned long long gbest;
    __shared__ unsigned long long best;
    __shared__ int cand_cols[NCBLK];
    __shared__ int full_tiles[NCBLK];
    __shared__ int ncand, nfull;

    const int row = blockIdx.x;
    const int tid = threadIdx.x;

    if (tid == 0) { gbest = ~0ull; best = ~0ull; ncand = 0; nfull = 0; }
    xs[tid]       = x[(size_t)row * F_DIM + tid];
    xs[tid + 128] = x[(size_t)row * F_DIM + tid + 128];
    keys[tid]       = g_top2[((size_t)row * NCBLK) * 2 + tid];
    keys[tid + 128] = g_top2[((size_t)row * NCBLK) * 2 + tid + 128];
    __syncthreads();

    unsigned long long lmin = keys[tid] < keys[tid + 128] ? keys[tid] : keys[tid + 128];
    atomicMin(&gbest, lmin);
    __syncthreads();

    const unsigned int kthresh = float_key(unkey((unsigned int)(gbest >> 32)) + MARGIN);

    {
        unsigned long long k1 = keys[2 * tid], k2 = keys[2 * tid + 1];
        if ((unsigned int)(k2 >> 32) < kthresh) {
            full_tiles[atomicAdd(&nfull, 1)] = tid;       // rare fallback
        } else if ((unsigned int)(k1 >> 32) < kthresh) {
            cand_cols[atomicAdd(&ncand, 1)] = (int)(k1 & 0xFFFFFFFFull);
        }
    }
    __syncthreads();

    for (int f = 0; f < nfull; f++) {
        int col = full_tiles[f] * BN + tid;
        const float* wr = w + (size_t)col * F_DIM;
        float dot = 0.f;
        #pragma unroll 8
        for (int k = 0; k < F_DIM; k++) dot += xs[k] * wr[k];
        float s = g_wsq[col] - 2.f * dot;
        unsigned long long key =
            ((unsigned long long)float_key(s) << 32) | (unsigned int)col;
        atomicMin(&best, key);
    }
    {
        int wid = tid >> 5, lane = tid & 31;
        for (int c = wid; c < ncand; c += 4) {
            int col = cand_cols[c];
            const float* wr = w + (size_t)col * F_DIM;
            float p = 0.f;
            #pragma unroll
            for (int k = lane; k < F_DIM; k += 32) p += xs[k] * wr[k];
            #pragma unroll
            for (int off = 16; off; off >>= 1) p += __shfl_down_sync(0xffffffffu, p, off);
            if (lane == 0) {
                float s = g_wsq[col] - 2.f * p;
                unsigned long long key =
                    ((unsigned long long)float_key(s) << 32) | (unsigned int)col;
                atomicMin(&best, key);
            }
        }
    }
    __syncthreads();

    if (tid == 0) {
        int idx = (int)(best & 0xFFFFFFFFull);
        out[row * 2 + 0] = (float)(idx >> 7);    // min_idx / 128
        out[row * 2 + 1] = (float)(idx & 127);   // min_idx % 128
    }
}

// ---------------------------------------------------------------------------
extern "C" void kernel_launch(void* const* d_in, const int* in_sizes, int n_in,
                              void* d_out, int out_size) {
    // Size-based input dispatch (xb: 1,048,576 elems; weights: 4,194,304).
    const float* xb;
    const float* w;
    int nx;
    if (in_sizes[0] <= in_sizes[1]) {
        xb = (const float*)d_in[0]; nx = in_sizes[0];
        w  = (const float*)d_in[1];
    } else {
        xb = (const float*)d_in[1]; nx = in_sizes[1];
        w  = (const float*)d_in[0];
    }
    float* out = (float*)d_out;
    const int B = nx / F_DIM;            // 4096

    som_convx_kernel<<<(nx / 4 + 255) / 256, 256>>>(xb, nx / 4);
    som_convw_kernel<<<M_TOTAL / 8, 256>>>(w);

    dim3 grid(NCBLK, B / BM);            // (128, 32)
    som_bf16_kernel<<<grid, 256>>>();

    som_rescore_kernel<<<B, 128>>>(xb, w, out);
}

// round 16
// speedup vs baseline: 5.1768x; 1.1837x over previous
#include <cuda_runtime.h>
#include <cuda_bf16.h>

// SOM forward (SIZE = (128,128,256), B = 4096), fp32 in, fp32 coords out.
// bf16 mma.sync filter GEMM (ldmatrix fragment loads) + exact fp32 rescore
// of candidates within a provable error margin -> exact argmin.
// NOTE: harness targets sm_100 (no 'a'): tcgen05/TMEM unavailable; legacy
// mma.sync is the best tensor path.
#define F_DIM 256
#define M_TOTAL 16384
#define B_MAX 4096

#define BM 128
#define BN 128
#define KC 32                 // k-chunk (bf16) staged in smem
#define KCP 40                // padded k-stride in halves (80B: 16B-aligned rows,
                              // ldmatrix-legal and bank-conflict-free)
#define NCBLK (M_TOTAL / BN)  // 128 column tiles

#define MARGIN 4.0f           // > worst-case two-sided bf16 dot error (~2.6)

__device__ float g_wsq[M_TOTAL];
__device__ __nv_bfloat16 g_xb[B_MAX * F_DIM];
__device__ __nv_bfloat16 g_wb[M_TOTAL * F_DIM];
// per (row, tile): top-2 packed keys (float_key(score)<<32 | global_col)
__device__ unsigned long long g_top2[B_MAX * NCBLK * 2];

// Monotone float <-> uint order maps (no NaNs in this workload)
__device__ __forceinline__ unsigned int float_key(float s) {
    unsigned int b = __float_as_uint(s);
    return b ^ ((b & 0x80000000u) ? 0xFFFFFFFFu : 0x80000000u);
}
__device__ __forceinline__ float unkey(unsigned int k) {
    return __uint_as_float((k & 0x80000000u) ? (k ^ 0x80000000u) : ~k);
}
__device__ __forceinline__ void top2_ins(unsigned long long& k1,
                                         unsigned long long& k2,
                                         unsigned long long a) {
    if (a < k1) { k2 = k1; k1 = a; }
    else if (a < k2) { k2 = a; }
}
__device__ __forceinline__ void ldsm_x4(unsigned int& r0, unsigned int& r1,
                                        unsigned int& r2, unsigned int& r3,
                                        unsigned int addr) {
    asm volatile("ldmatrix.sync.aligned.m8n8.x4.shared.b16 {%0,%1,%2,%3}, [%4];"
                 : "=r"(r0), "=r"(r1), "=r"(r2), "=r"(r3) : "r"(addr));
}

// ---------------------------------------------------------------------------
// Convert x -> bf16. One float4 per thread.
// ---------------------------------------------------------------------------
__global__ void som_convx_kernel(const float* __restrict__ x, int n4) {
    int i = blockIdx.x * blockDim.x + threadIdx.x;
    if (i >= n4) return;
    float4 v = reinterpret_cast<const float4*>(x)[i];
    __nv_bfloat162 p0 = __floats2bfloat162_rn(v.x, v.y);
    __nv_bfloat162 p1 = __floats2bfloat162_rn(v.z, v.w);
    uint2 st = make_uint2(*reinterpret_cast<unsigned int*>(&p0),
                          *reinterpret_cast<unsigned int*>(&p1));
    *reinterpret_cast<uint2*>(&g_xb[i * 4]) = st;
}

// ---------------------------------------------------------------------------
// Convert w -> bf16 AND compute exact fp32 wsq. One warp per codebook row.
// ---------------------------------------------------------------------------
__global__ void som_convw_kernel(const float* __restrict__ w) {
    int row  = (blockIdx.x * blockDim.x + threadIdx.x) >> 5;
    int lane = threadIdx.x & 31;
    if (row >= M_TOTAL) return;
    const float4* p = reinterpret_cast<const float4*>(w + (size_t)row * F_DIM);
    float s = 0.f;
    #pragma unroll
    for (int c = lane; c < F_DIM / 4; c += 32) {
        float4 v = p[c];
        s += v.x * v.x + v.y * v.y + v.z * v.z + v.w * v.w;
        __nv_bfloat162 p0 = __floats2bfloat162_rn(v.x, v.y);
        __nv_bfloat162 p1 = __floats2bfloat162_rn(v.z, v.w);
        uint2 st = make_uint2(*reinterpret_cast<unsigned int*>(&p0),
                              *reinterpret_cast<unsigned int*>(&p1));
        *reinterpret_cast<uint2*>(&g_wb[(size_t)row * F_DIM + c * 4]) = st;
    }
    #pragma unroll
    for (int off = 16; off; off >>= 1) s += __shfl_down_sync(0xffffffffu, s, off);
    if (lane == 0) g_wsq[row] = s;
}

// ---------------------------------------------------------------------------
// bf16 tensor GEMM + per-(row,tile) top-2 epilogue.
// 8 warps: warp_m = wid&1 (64 rows), warp_n = wid>>1 (32 cols); each warp
// 4x4 m16n8k16 tiles. ldmatrix.x4 fragment loads (22 instr / 16 mma).
// ---------------------------------------------------------------------------
__global__ __launch_bounds__(256, 2)
void som_bf16_kernel() {
    __shared__ __align__(16) __nv_bfloat16 As[2][BM][KCP];  // [row][k], 80B rows
    __shared__ __align__(16) __nv_bfloat16 Bs[2][BN][KCP];  // [col][k]
    __shared__ unsigned long long stop2[BM][4][2];          // per row, warp_n

    const int tid  = threadIdx.x;
    const int bx   = blockIdx.x;       // column tile (0..127)
    const int by   = blockIdx.y;       // row tile    (0..31)
    const int wid  = tid >> 5;
    const int lane = tid & 31;
    const int warp_m = wid & 1;
    const int warp_n = wid >> 1;
    const int m_base = warp_m * 64;
    const int n_base = warp_n * 32;
    const int lg = lane >> 2;          // 0..7
    const int lt = lane & 3;           // 0..3

    // ldmatrix lane-addressing components (verified fragment mappings)
    const int a_row  = lane & 15;            // row within 16-row tile
    const int a_koff = (lane >> 4) << 3;     // 0 or 8 (k half)
    const int b_nrow = ((lane >> 4) << 3) + (lane & 7);  // n row within 16
    const int b_koff = ((lane >> 3) & 1) << 3;           // 0 or 8

    // loader mapping: thread t loads uint4 (r0,q0) and (r0+64,q0) per matrix.
    const int r0 = tid >> 2;           // 0..63
    const int q0 = tid & 3;            // halves q0*8
    const __nv_bfloat16* xg0 = g_xb + (size_t)(by * BM + r0)      * F_DIM + q0 * 8;
    const __nv_bfloat16* xg1 = g_xb + (size_t)(by * BM + r0 + 64) * F_DIM + q0 * 8;
    const __nv_bfloat16* wg0 = g_wb + (size_t)(bx * BN + r0)      * F_DIM + q0 * 8;
    const __nv_bfloat16* wg1 = g_wb + (size_t)(bx * BN + r0 + 64) * F_DIM + q0 * 8;

    float acc[4][4][4];
    #pragma unroll
    for (int mt = 0; mt < 4; mt++)
        #pragma unroll
        for (int nt = 0; nt < 4; nt++)
            #pragma unroll
            for (int r = 0; r < 4; r++) acc[mt][nt][r] = 0.f;

    // 16B-aligned single vector store (KCP=40 -> 80B rows, q0*16B offset)
    auto st8 = [&](__nv_bfloat16* dst, uint4 v) {
        *reinterpret_cast<uint4*>(dst) = v;
    };

    // preload chunk 0
    {
        uint4 a0 = *reinterpret_cast<const uint4*>(xg0);
        uint4 a1 = *reinterpret_cast<const uint4*>(xg1);
        uint4 b0 = *reinterpret_cast<const uint4*>(wg0);
        uint4 b1 = *reinterpret_cast<const uint4*>(wg1);
        st8(&As[0][r0     ][q0 * 8], a0);
        st8(&As[0][r0 + 64][q0 * 8], a1);
        st8(&Bs[0][r0     ][q0 * 8], b0);
        st8(&Bs[0][r0 + 64][q0 * 8], b1);
    }
    __syncthreads();

    const int NKC = F_DIM / KC;   // 8 chunks
    for (int kt = 0; kt < NKC; kt++) {
        const int cur = kt & 1;
        uint4 pa0, pa1, pb0, pb1;
        if (kt < NKC - 1) {       // register-staged prefetch
            pa0 = *reinterpret_cast<const uint4*>(xg0 + (kt + 1) * KC);
            pa1 = *reinterpret_cast<const uint4*>(xg1 + (kt + 1) * KC);
            pb0 = *reinterpret_cast<const uint4*>(wg0 + (kt + 1) * KC);
            pb1 = *reinterpret_cast<const uint4*>(wg1 + (kt + 1) * KC);
        }
        #pragma unroll
        for (int ks = 0; ks < KC; ks += 16) {
            // A fragments: one ldmatrix.x4 per mt (16x16 tile)
            unsigned int afr[4][4];
            #pragma unroll
            for (int mt = 0; mt < 4; mt++) {
                unsigned int addr = (unsigned int)__cvta_generic_to_shared(
                    &As[cur][m_base + mt * 16 + a_row][ks + a_koff]);
                ldsm_x4(afr[mt][0], afr[mt][1], afr[mt][2], afr[mt][3], addr);
            }
            // B fragments: one ldmatrix.x4 per nt-pair (16 n-rows x 16 k)
            unsigned int bfr[4][2];
            #pragma unroll
            for (int p = 0; p < 2; p++) {
                unsigned int addr = (unsigned int)__cvta_generic_to_shared(
                    &Bs[cur][n_base + p * 16 + b_nrow][ks + b_koff]);
                ldsm_x4(bfr[2 * p][0], bfr[2 * p][1],
                        bfr[2 * p + 1][0], bfr[2 * p + 1][1], addr);
            }
            #pragma unroll
            for (int mt = 0; mt < 4; mt++)
                #pragma unroll
                for (int nt = 0; nt < 4; nt++) {
                    asm volatile(
                        "mma.sync.aligned.m16n8k16.row.col.f32.bf16.bf16.f32 "
                        "{%0,%1,%2,%3}, {%4,%5,%6,%7}, {%8,%9}, {%0,%1,%2,%3};\n"
                        : "+f"(acc[mt][nt][0]), "+f"(acc[mt][nt][1]),
                          "+f"(acc[mt][nt][2]), "+f"(acc[mt][nt][3])
                        : "r"(afr[mt][0]), "r"(afr[mt][1]),
                          "r"(afr[mt][2]), "r"(afr[mt][3]),
                          "r"(bfr[nt][0]), "r"(bfr[nt][1]));
                }
        }
        if (kt < NKC - 1) {
            const int nxt = cur ^ 1;
            st8(&As[nxt][r0     ][q0 * 8], pa0);
            st8(&As[nxt][r0 + 64][q0 * 8], pa1);
            st8(&Bs[nxt][r0     ][q0 * 8], pb0);
            st8(&Bs[nxt][r0 + 64][q0 * 8], pb1);
            __syncthreads();
        }
    }

    // Epilogue: approx score = wsq - 2*dot; top-2 per (row, tile).
    // D frag: c0,c1 -> (row lg, cols 2lt,2lt+1); c2,c3 -> (row lg+8, same).
    #pragma unroll
    for (int mt = 0; mt < 4; mt++) {
        #pragma unroll
        for (int h = 0; h < 2; h++) {
            int row_local = m_base + mt * 16 + lg + h * 8;
            unsigned long long k1 = ~0ull, k2 = ~0ull;
            #pragma unroll
            for (int nt = 0; nt < 4; nt++) {
                #pragma unroll
                for (int j = 0; j < 2; j++) {
                    int col = bx * BN + n_base + nt * 8 + 2 * lt + j;
                    float s = g_wsq[col] - 2.f * acc[mt][nt][h * 2 + j];
                    unsigned long long key =
                        ((unsigned long long)float_key(s) << 32) | (unsigned int)col;
                    top2_ins(k1, k2, key);
                }
            }
            #pragma unroll
            for (int off = 1; off <= 2; off <<= 1) {
                unsigned long long o1 = __shfl_xor_sync(0xffffffffu, k1, off);
                unsigned long long o2 = __shfl_xor_sync(0xffffffffu, k2, off);
                top2_ins(k1, k2, o1);
                top2_ins(k1, k2, o2);
            }
            if (lt == 0) {
                stop2[row_local][warp_n][0] = k1;
                stop2[row_local][warp_n][1] = k2;
            }
        }
    }
    __syncthreads();

    if (tid < BM) {
        unsigned long long k1 = stop2[tid][0][0], k2 = stop2[tid][0][1];
        #pragma unroll
        for (int wn = 1; wn < 4; wn++) {
            top2_ins(k1, k2, stop2[tid][wn][0]);
            top2_ins(k1, k2, stop2[tid][wn][1]);
        }
        const int grow = by * BM + tid;
        g_top2[((size_t)grow * NCBLK + bx) * 2 + 0] = k1;
        g_top2[((size_t)grow * NCBLK + bx) * 2 + 1] = k2;
    }
}

// ---------------------------------------------------------------------------
// Rescore: per row, approx global min -> candidates within MARGIN -> exact
// fp32 rescore -> exact argmin coords (fp32 output; harness compares fp32).
// ---------------------------------------------------------------------------
__global__ void som_rescore_kernel(const float* __restrict__ x,
                                   const float* __restrict__ w,
                                   float* __restrict__ out) {
    __shared__ float xs[F_DIM];
    __shared__ unsigned long long keys[NCBLK * 2];
    __shared__ unsigned long long gbest;
    __shared__ unsigned long long best;
    __shared__ int cand_cols[NCBLK];
    __shared__ int full_tiles[NCBLK];
    __shared__ int ncand, nfull;

    const int row = blockIdx.x;
    const int tid = threadIdx.x;

    if (tid == 0) { gbest = ~0ull; best = ~0ull; ncand = 0; nfull = 0; }
    xs[tid]       = x[(size_t)row * F_DIM + tid];
    xs[tid + 128] = x[(size_t)row * F_DIM + tid + 128];
    keys[tid]       = g_top2[((size_t)row * NCBLK) * 2 + tid];
    keys[tid + 128] = g_top2[((size_t)row * NCBLK) * 2 + tid + 128];
    __syncthreads();

    unsigned long long lmin = keys[tid] < keys[tid + 128] ? keys[tid] : keys[tid + 128];
    atomicMin(&gbest, lmin);
    __syncthreads();

    const unsigned int kthresh = float_key(unkey((unsigned int)(gbest >> 32)) + MARGIN);

    {
        unsigned long long k1 = keys[2 * tid], k2 = keys[2 * tid + 1];
        if ((unsigned int)(k2 >> 32) < kthresh) {
            full_tiles[atomicAdd(&nfull, 1)] = tid;       // rare fallback
        } else if ((unsigned int)(k1 >> 32) < kthresh) {
            cand_cols[atomicAdd(&ncand, 1)] = (int)(k1 & 0xFFFFFFFFull);
        }
    }
    __syncthreads();

    for (int f = 0; f < nfull; f++) {
        int col = full_tiles[f] * BN + tid;
        const float* wr = w + (size_t)col * F_DIM;
        float dot = 0.f;
        #pragma unroll 8
        for (int k = 0; k < F_DIM; k++) dot += xs[k] * wr[k];
        float s = g_wsq[col] - 2.f * dot;
        unsigned long long key =
            ((unsigned long long)float_key(s) << 32) | (unsigned int)col;
        atomicMin(&best, key);
    }
    {
        int wd = tid >> 5, lane = tid & 31;
        for (int c = wd; c < ncand; c += 4) {
            int col = cand_cols[c];
            const float* wr = w + (size_t)col * F_DIM;
            float p = 0.f;
            #pragma unroll
            for (int k = lane; k < F_DIM; k += 32) p += xs[k] * wr[k];
            #pragma unroll
            for (int off = 16; off; off >>= 1) p += __shfl_down_sync(0xffffffffu, p, off);
            if (lane == 0) {
                float s = g_wsq[col] - 2.f * p;
                unsigned long long key =
                    ((unsigned long long)float_key(s) << 32) | (unsigned int)col;
                atomicMin(&best, key);
            }
        }
    }
    __syncthreads();

    if (tid == 0) {
        int idx = (int)(best & 0xFFFFFFFFull);
        out[row * 2 + 0] = (float)(idx >> 7);    // min_idx / 128
        out[row * 2 + 1] = (float)(idx & 127);   // min_idx % 128
    }
}

// ---------------------------------------------------------------------------
extern "C" void kernel_launch(void* const* d_in, const int* in_sizes, int n_in,
                              void* d_out, int out_size) {
    // Size-based input dispatch (xb: 1,048,576 elems; weights: 4,194,304).
    const float* xb;
    const float* w;
    int nx;
    if (in_sizes[0] <= in_sizes[1]) {
        xb = (const float*)d_in[0]; nx = in_sizes[0];
        w  = (const float*)d_in[1];
    } else {
        xb = (const float*)d_in[1]; nx = in_sizes[1];
        w  = (const float*)d_in[0];
    }
    float* out = (float*)d_out;
    const int B = nx / F_DIM;            // 4096

    som_convx_kernel<<<(nx / 4 + 255) / 256, 256>>>(xb, nx / 4);
    som_convw_kernel<<<M_TOTAL / 8, 256>>>(w);

    dim3 grid(NCBLK, B / BM);            // (128, 32)
    som_bf16_kernel<<<grid, 256>>>();

    som_rescore_kernel<<<B, 128>>>(xb, w, out);
}